// round 12
// baseline (speedup 1.0000x reference)
#include <cuda_runtime.h>
#include <stdint.h>

#define NB 64
#define CH 64
#define TT 300
#define VV 25
#define SS 3
#define ICH 16
#define TV 7500

// ---------------- scratch ----------------
__device__ float g_T1[SS * NB * ICH * TV];
__device__ float g_T2[SS * NB * ICH * TV];
__device__ __align__(16) uint32_t g_Wb2[9 * 32 * 96];   // conv B: [kt][c2][n96] bf16x2
__device__ __align__(16) uint32_t g_Wh[SS * CH * CH];   // [s][c][o] tf32 (slim-scaled)
__device__ float g_bT1e[SS * ICH];
__device__ float g_bT2e[SS * ICH];
__device__ float g_btot[CH];
__device__ float g_bnscale[CH];
__device__ float g_bnbias[CH];
__device__ float g_Afull[SS * VV * VV];
__device__ float g_A1[SS * NB * VV * VV];

// ---------------- helpers ----------------
__device__ __forceinline__ uint32_t f2tf32(float f) {
    uint32_t r;
    asm("cvt.rna.tf32.f32 %0, %1;" : "=r"(r) : "f"(f));
    return r;
}
__device__ __forceinline__ uint32_t pack_bf16x2(float lo, float hi) {
    uint32_t r;
    asm("cvt.rn.bf16x2.f32 %0, %1, %2;" : "=r"(r) : "f"(hi), "f"(lo));
    return r;
}
__device__ __forceinline__ uint32_t smem_u32(const void* p) {
    uint32_t a;
    asm("{ .reg .u64 t; cvta.to.shared.u64 t, %1; cvt.u32.u64 %0, t; }" : "=r"(a) : "l"(p));
    return a;
}
__device__ __forceinline__ void cp16(uint32_t dst, const void* src) {
    asm volatile("cp.async.cg.shared.global [%0], [%1], 16;" :: "r"(dst), "l"(src));
}
__device__ __forceinline__ void cp_commit() {
    asm volatile("cp.async.commit_group;" ::: "memory");
}
template <int N>
__device__ __forceinline__ void cp_wait() {
    asm volatile("cp.async.wait_group %0;" :: "n"(N) : "memory");
}
__device__ __forceinline__ void mma_bf16(float* c, const uint32_t* a, const uint32_t* b) {
    asm volatile(
        "mma.sync.aligned.m16n8k16.row.col.f32.bf16.bf16.f32 "
        "{%0,%1,%2,%3}, {%4,%5,%6,%7}, {%8,%9}, {%0,%1,%2,%3};"
        : "+f"(c[0]), "+f"(c[1]), "+f"(c[2]), "+f"(c[3])
        : "r"(a[0]), "r"(a[1]), "r"(a[2]), "r"(a[3]), "r"(b[0]), "r"(b[1]));
}
__device__ __forceinline__ void mma_tf32(float* c, const uint32_t* a, const uint32_t* b) {
    asm volatile(
        "mma.sync.aligned.m16n8k8.row.col.f32.tf32.tf32.f32 "
        "{%0,%1,%2,%3}, {%4,%5,%6,%7}, {%8,%9}, {%0,%1,%2,%3};"
        : "+f"(c[0]), "+f"(c[1]), "+f"(c[2]), "+f"(c[3])
        : "r"(a[0]), "r"(a[1]), "r"(a[2]), "r"(a[3]), "r"(b[0]), "r"(b[1]));
}
__device__ __forceinline__ float slim16(int ic, const float* w) {
    if (ic < 9)  return 1.f;
    if (ic < 11) return w[1];
    if (ic < 12) return w[2];
    if (ic < 14) return w[3];
    return w[4];
}
__device__ __forceinline__ float slim64(int o, const float* w) {
    if (o < 38) return 1.f;
    if (o < 44) return w[1];
    if (o < 51) return w[2];
    if (o < 57) return w[3];
    return w[4];
}

// ---------------- prep (index 0) ----------------
__global__ void prep_kernel(const float* __restrict__ w5,
                            const float* __restrict__ A, const float* __restrict__ PA,
                            const float* __restrict__ Wd, const float* __restrict__ bd,
                            const float* __restrict__ WT1, const float* __restrict__ bT1,
                            const float* __restrict__ WT2, const float* __restrict__ bT2,
                            const float* __restrict__ bng, const float* __restrict__ bnb,
                            const float* __restrict__ bnm, const float* __restrict__ bnv)
{
    int tid = threadIdx.x + blockIdx.x * blockDim.x;
    int nt = blockDim.x * gridDim.x;

    for (int i = tid; i < SS * VV * VV; i += nt) {
        float a = A[i];
        float a2 = a * a;
        float ach = 8.f * a2 * a2 - 4.f * a2 - 4.f * a;
        int u = (i / VV) % VV, v = i % VV;
        g_Afull[i] = a + PA[i] + ach + (u == v ? 1.f : 0.f);
    }
    for (int i = tid; i < 9 * 32 * 96; i += nt) {
        int n96 = i % 96;
        int c2 = (i / 96) % 32;
        int kt = i / (96 * 32);
        int s = n96 >> 5;
        int ic2 = n96 & 31;
        int ic = ic2 & 15;
        const float* src = (ic2 < 16) ? WT1 : WT2;
        float sc = slim16(ic, w5);
        float v0 = src[((s * ICH + ic) * CH + 2 * c2) * 9 + kt] * sc;
        float v1 = src[((s * ICH + ic) * CH + 2 * c2 + 1) * 9 + kt] * sc;
        g_Wb2[i] = pack_bf16x2(v0, v1);
    }
    for (int i = tid; i < SS * ICH; i += nt) {
        int ic = i % ICH;
        float sc = slim16(ic, w5);
        g_bT1e[i] = bT1[i] * sc;
        g_bT2e[i] = bT2[i] * sc;
    }
    for (int i = tid; i < SS * CH * CH; i += nt) {
        int o = i & 63;
        int c = (i >> 6) & 63;
        int s = i >> 12;
        g_Wh[i] = f2tf32(Wd[(s * CH + o) * CH + c] * slim64(o, w5));
    }
    for (int i = tid; i < CH; i += nt) {
        float bt = 0.f;
        for (int s = 0; s < SS; ++s) bt += bd[s * CH + i];
        g_btot[i] = bt * slim64(i, w5);
        float inv = rsqrtf(bnv[i] + 1e-5f);
        float bs = bng[i] * inv;
        g_bnscale[i] = bs;
        g_bnbias[i] = bnb[i] - bnm[i] * bs;
    }
}

// ---------------- bf16 mma conv: t-tile 5, 3-slot ring (index 1) -----------
#define XROWS 328
#define XS2_U32 (32 * XROWS)
#define BSTR 104
#define BS2_U32 (32 * BSTR)
#define CONV_SMEM ((XS2_U32 + 3 * BS2_U32) * 4)

__global__ void __launch_bounds__(256, 2) tc_conv(const float* __restrict__ x)
{
    extern __shared__ uint32_t sm[];
    uint32_t* xs = sm;
    uint32_t* bs = sm + XS2_U32;
    const uint32_t bs_addr = smem_u32(sm) + XS2_U32 * 4;

    const int tid = threadIdx.x;
    const int warp = tid >> 5;
    const int lane = tid & 31;
    const int lr = lane & 3;
    const int lq = lane >> 2;
    const int wm = warp & 3;
    const int wn = warp >> 2;
    const int t0 = blockIdx.x * 5;
    const int n = blockIdx.y;

    // x tile: rows r -> (t0-4 + r/25, r%25), r < 325 valid
    for (int c2 = warp; c2 < 32; c2 += 8) {
        const float* x0 = x + ((n * CH + 2 * c2) * TT + (t0 - 4)) * VV;
        for (int r = lane; r < XROWS; r += 32) {
            float v0 = 0.f, v1 = 0.f;
            if (r < 325) {
                int t = t0 - 4 + r / 25;
                if (t >= 0 && t < TT) { v0 = x0[r]; v1 = x0[r + TT * VV]; }
            }
            xs[c2 * XROWS + r] = pack_bf16x2(v0, v1);
        }
    }

    // prologue: B[kt=0] into slot 0
#pragma unroll
    for (int j = 0; j < 3; ++j) {
        int f = tid + j * 256;
        int c2 = f / 24, off = (f % 24) * 4;
        cp16(bs_addr + (c2 * BSTR + off) * 4, g_Wb2 + c2 * 96 + off);
    }
    cp_commit();

    float acc[2][6][4];
#pragma unroll
    for (int mi = 0; mi < 2; ++mi)
#pragma unroll
        for (int ni = 0; ni < 6; ++ni)
#pragma unroll
            for (int q = 0; q < 4; ++q) acc[mi][ni][q] = 0.f;

#pragma unroll 1
    for (int kt = 0; kt < 9; ++kt) {
        if (kt < 8) {
            // issue B[kt+1] into slot (kt+1)%3 (safe: readers are >= kt-1)
            const int wslot = (kt + 1) % 3;
            const uint32_t dstb = bs_addr + wslot * BS2_U32 * 4;
            const uint32_t* src = g_Wb2 + (kt + 1) * 3072;
#pragma unroll
            for (int j = 0; j < 3; ++j) {
                int f = tid + j * 256;
                int c2 = f / 24, off = (f % 24) * 4;
                cp16(dstb + (c2 * BSTR + off) * 4, src + c2 * 96 + off);
            }
            cp_commit();
            cp_wait<1>();
        } else {
            cp_wait<0>();
        }
        __syncthreads();   // B[kt] visible; xs visible on first iter

        const uint32_t* bsl = bs + (kt % 3) * BS2_U32;
        const int rowoff = kt * 25 + lq;

#pragma unroll
        for (int ks = 0; ks < 4; ++ks) {
            const int kb2 = ks * 8;
            uint32_t af[2][4];
#pragma unroll
            for (int mi = 0; mi < 2; ++mi) {
                int R = wm * 32 + mi * 16 + rowoff;
                const uint32_t* p0 = &xs[(kb2 + lr) * XROWS + R];
                af[mi][0] = p0[0];
                af[mi][1] = p0[8];
                af[mi][2] = p0[4 * XROWS];
                af[mi][3] = p0[4 * XROWS + 8];
            }
            uint32_t bf[6][2];
#pragma unroll
            for (int ni = 0; ni < 6; ++ni) {
                int cb = wn * 48 + ni * 8 + lq;
                bf[ni][0] = bsl[(kb2 + lr) * BSTR + cb];
                bf[ni][1] = bsl[(kb2 + lr + 4) * BSTR + cb];
            }
#pragma unroll
            for (int mi = 0; mi < 2; ++mi)
#pragma unroll
                for (int ni = 0; ni < 6; ++ni)
                    mma_bf16(acc[mi][ni], af[mi], bf[ni]);
        }
    }

#pragma unroll
    for (int mi = 0; mi < 2; ++mi) {
        const int rb = wm * 32 + mi * 16 + lq;
#pragma unroll
        for (int ni = 0; ni < 6; ++ni) {
            const int cb = wn * 48 + ni * 8 + 2 * lr;
#pragma unroll
            for (int q = 0; q < 4; ++q) {
                int row = rb + (q >> 1) * 8;
                int col = cb + (q & 1);
                if (row < 125) {
                    int s = col >> 5;
                    int ic2 = col & 31;
                    int ic = ic2 & 15;
                    float bias, *dst;
                    if (ic2 < 16) { bias = g_bT1e[s * ICH + ic]; dst = g_T1; }
                    else          { bias = g_bT2e[s * ICH + ic]; dst = g_T2; }
                    dst[((s * NB + n) * ICH + ic) * TV + t0 * 25 + row] = acc[mi][ni][q] + bias;
                }
            }
        }
    }
}

// ---------------- attention + softmax merged (index 2) ----------------
__global__ void __launch_bounds__(128) attsoft_kernel()
{
    __shared__ __align__(16) float t1s[2000];
    __shared__ __align__(16) float t2s[2000];
    __shared__ float red[3125];
    const int tid = threadIdx.x;
    const int b = blockIdx.x;                 // s*64+n
    const float* p1 = &g_T1[b * (ICH * TV)];
    const float* p2 = &g_T2[b * (ICH * TV)];

    const bool active = tid < 125;
    const int ks = tid / 25;
    const int tq = (tid % 25) / 5;
    const int tk = tid % 5;

    float acc[5][5];
#pragma unroll
    for (int i = 0; i < 5; ++i)
#pragma unroll
        for (int j = 0; j < 5; ++j) acc[i][j] = 0.f;

#pragma unroll 1
    for (int chk = 0; chk < 60; ++chk) {
        __syncthreads();
        {
            const float4* s1 = (const float4*)(p1 + chk * 2000);
            const float4* s2 = (const float4*)(p2 + chk * 2000);
            for (int i = tid; i < 500; i += 128) {
                ((float4*)t1s)[i] = s1[i];
                ((float4*)t2s)[i] = s2[i];
            }
        }
        __syncthreads();
        if (active) {
            const int kb = ks * 16;
#pragma unroll 2
            for (int kl = 0; kl < 16; ++kl) {
                const float* r1 = &t1s[(kb + kl) * 25 + tq * 5];
                const float* r2 = &t2s[(kb + kl) * 25 + tk * 5];
                float t1v[5], t2v[5];
#pragma unroll
                for (int i = 0; i < 5; ++i) t1v[i] = r1[i];
#pragma unroll
                for (int j = 0; j < 5; ++j) t2v[j] = r2[j];
#pragma unroll
                for (int i = 0; i < 5; ++i)
#pragma unroll
                    for (int j = 0; j < 5; ++j)
                        acc[i][j] += t1v[i] * t2v[j];
            }
        }
    }

    __syncthreads();
    if (active) {
#pragma unroll
        for (int i = 0; i < 5; ++i)
#pragma unroll
            for (int j = 0; j < 5; ++j)
                red[ks * 625 + (tq * 5 + i) * 25 + tk * 5 + j] = acc[i][j];
    }
    __syncthreads();

    // softmax over vq per vk, then A1 = A_full + att
    if (tid < 25) {
        const int vk = tid;
        const int s = b / NB;
        float r[25];
        float mx = -1e30f;
#pragma unroll 1
        for (int vq = 0; vq < 25; ++vq) {
            int o = vq * 25 + vk;
            float sum = red[o] + red[625 + o] + red[1250 + o] + red[1875 + o] + red[2500 + o];
            r[vq] = sum * (1.f / 4800.f);
            mx = fmaxf(mx, r[vq]);
        }
        float e = 0.f;
#pragma unroll 1
        for (int vq = 0; vq < 25; ++vq) { r[vq] = expf(r[vq] - mx); e += r[vq]; }
        float inv = 1.f / e;
#pragma unroll 1
        for (int vq = 0; vq < 25; ++vq)
            g_A1[b * 625 + vq * 25 + vk] = g_Afull[s * 625 + vq * 25 + vk] + r[vq] * inv;
    }
}

// ---------------- fused z: t-tile 5 (index 3: profiled) ----------------
// stage1: h[p128 x o64] = xB^T . wB, K=64, p<125 valid
// stage2: z[r=(tl,o) 320 x v32] += hs^T . a1t_s, K=32, over s
#define FZ_XB_STR 136
#define FZ_XB (64 * FZ_XB_STR)            // 8704
#define FZ_WB_STR 72
#define FZ_WB (64 * FZ_WB_STR)            // 4608
#define FZ_HS_STR 328
#define FZ_HS (32 * FZ_HS_STR)            // 10496
#define FZ_A1_STR 36
#define FZ_A1S (32 * FZ_A1_STR)           // 1152 per s
#define FZ_SMEM ((FZ_XB + FZ_WB + FZ_HS + 3 * FZ_A1S) * 4)

__global__ void __launch_bounds__(256, 2) fz_kernel(const float* __restrict__ x,
                                                    float* __restrict__ out)
{
    extern __shared__ uint32_t smz[];
    uint32_t* xB  = smz;                          // [c][p] tf32
    uint32_t* wB  = smz + FZ_XB;                  // [c][o] tf32
    uint32_t* hs  = smz + FZ_XB + FZ_WB;          // [u][tl*64+o] tf32
    uint32_t* a1t = smz + FZ_XB + FZ_WB + FZ_HS;  // [s][v][u] tf32

    const int tid = threadIdx.x;
    const int warp = tid >> 5;
    const int lane = tid & 31;
    const int lr = lane & 3;
    const int lq = lane >> 2;
    const int nt = warp >> 1;            // stage2 n-tile (0..3)
    const int mtb = (warp & 1) * 10;     // stage2 m-tile base
    const int t0 = blockIdx.x * 5;
    const int p0 = t0 * 25;
    const int n = blockIdx.y;

    // stage x tile [c][p] (125 valid, pad 136)
    for (int i = tid; i < FZ_XB; i += 256) {
        int c = i / FZ_XB_STR, p = i % FZ_XB_STR;
        xB[i] = (p < 125) ? f2tf32(x[(n * CH + c) * TV + p0 + p]) : 0u;
    }
    // stage A1^T all s: a1t[s][v][u]
    for (int i = tid; i < 3 * 1024; i += 256) {
        int s = i >> 10;
        int v = (i >> 5) & 31;
        int u = i & 31;
        uint32_t val = 0u;
        if (v < VV && u < VV)
            val = f2tf32(g_A1[(s * NB + n) * 625 + u * 25 + v]);
        a1t[s * FZ_A1S + v * FZ_A1_STR + u] = val;
    }
    // zero hs pad rows u = 25..31
    for (int i = tid; i < 7 * FZ_HS_STR; i += 256)
        hs[25 * FZ_HS_STR + i] = 0u;

    float acc2[10][4];
#pragma unroll
    for (int ti = 0; ti < 10; ++ti)
#pragma unroll
        for (int q = 0; q < 4; ++q) acc2[ti][q] = 0.f;

#pragma unroll 1
    for (int s = 0; s < SS; ++s) {
        __syncthreads();   // prev stage2 reads done; wB/hs free
        for (int i = tid; i < 4096; i += 256) {
            int c = i >> 6, o = i & 63;
            wB[c * FZ_WB_STR + o] = g_Wh[s * 4096 + i];
        }
        __syncthreads();

        // ---- stage1: h = x^T . W ----
        float acc1[8][4];
#pragma unroll
        for (int ni = 0; ni < 8; ++ni)
#pragma unroll
            for (int q = 0; q < 4; ++q) acc1[ni][q] = 0.f;

#pragma unroll
        for (int kk = 0; kk < 8; ++kk) {
            const int kb = kk * 8;
            uint32_t af[4];
            {
                const uint32_t* pA = &xB[(kb + lr) * FZ_XB_STR + warp * 16 + lq];
                af[0] = pA[0];
                af[1] = pA[8];
                af[2] = pA[4 * FZ_XB_STR];
                af[3] = pA[4 * FZ_XB_STR + 8];
            }
#pragma unroll
            for (int ni = 0; ni < 8; ++ni) {
                uint32_t bf[2];
                const uint32_t* pB = &wB[(kb + lr) * FZ_WB_STR + ni * 8 + lq];
                bf[0] = pB[0];
                bf[1] = pB[4 * FZ_WB_STR];
                mma_tf32(acc1[ni], af, bf);
            }
        }

        // ---- transpose-store h into hs[u][tl*64+o] ----
#pragma unroll
        for (int ni = 0; ni < 8; ++ni)
#pragma unroll
            for (int q = 0; q < 4; ++q) {
                int p = warp * 16 + lq + (q >> 1) * 8;
                int o = ni * 8 + 2 * lr + (q & 1);
                if (p < 125) {
                    int tl = p / 25, u = p % 25;
                    hs[u * FZ_HS_STR + tl * 64 + o] = f2tf32(acc1[ni][q]);
                }
            }
        __syncthreads();

        // ---- stage2: z += hs^T . a1t_s (warp: 10 m-tiles x 1 n-tile) ----
#pragma unroll
        for (int kk = 0; kk < 4; ++kk) {
            const int kb = kk * 8;
            uint32_t bf[2];
            {
                const uint32_t* pB = &a1t[s * FZ_A1S + (nt * 8 + lq) * FZ_A1_STR + kb + lr];
                bf[0] = pB[0];
                bf[1] = pB[4];
            }
#pragma unroll
            for (int ti = 0; ti < 10; ++ti) {
                const int mt = mtb + ti;
                uint32_t af[4];
                const uint32_t* pA = &hs[(kb + lr) * FZ_HS_STR + mt * 16 + lq];
                af[0] = pA[0];
                af[1] = pA[8];
                af[2] = pA[4 * FZ_HS_STR];
                af[3] = pA[4 * FZ_HS_STR + 8];
                mma_tf32(acc2[ti], af, bf);
            }
        }
    }

    // epilogue: BN + residual + relu
#pragma unroll
    for (int ti = 0; ti < 10; ++ti) {
        const int mt = mtb + ti;
#pragma unroll
        for (int q = 0; q < 4; ++q) {
            int r = mt * 16 + lq + (q >> 1) * 8;
            int v = nt * 8 + 2 * lr + (q & 1);
            if (v < VV) {
                int tl = r >> 6, o = r & 63;
                int gi = ((n * CH + o) * TT + t0 + tl) * VV + v;
                float val = fmaf(acc2[ti][q] + g_btot[o], g_bnscale[o], g_bnbias[o]) + x[gi];
                out[gi] = fmaxf(val, 0.f);
            }
        }
    }
}

// ---------------- launch ----------------
extern "C" void kernel_launch(void* const* d_in, const int* in_sizes, int n_in,
                              void* d_out, int out_size)
{
    const float* x   = (const float*)d_in[0];
    const float* w5  = (const float*)d_in[1];
    const float* A   = (const float*)d_in[2];
    const float* PA  = (const float*)d_in[3];
    const float* Wd  = (const float*)d_in[4];
    const float* bd  = (const float*)d_in[5];
    const float* WT1 = (const float*)d_in[6];
    const float* bT1 = (const float*)d_in[7];
    const float* WT2 = (const float*)d_in[8];
    const float* bT2 = (const float*)d_in[9];
    const float* bng = (const float*)d_in[10];
    const float* bnb = (const float*)d_in[11];
    const float* bnm = (const float*)d_in[12];
    const float* bnv = (const float*)d_in[13];
    float* out = (float*)d_out;

    cudaFuncSetAttribute(tc_conv,  cudaFuncAttributeMaxDynamicSharedMemorySize, CONV_SMEM);
    cudaFuncSetAttribute(fz_kernel, cudaFuncAttributeMaxDynamicSharedMemorySize, FZ_SMEM);

    prep_kernel<<<4, 256>>>(w5, A, PA, Wd, bd, WT1, bT1, WT2, bT2, bng, bnb, bnm, bnv);
    tc_conv<<<dim3(60, NB), 256, CONV_SMEM>>>(x);
    attsoft_kernel<<<SS * NB, 128>>>();
    fz_kernel<<<dim3(60, NB), 256, FZ_SMEM>>>(x, out);   // profiled slot (index 3)
}

// round 15
// speedup vs baseline: 1.1752x; 1.1752x over previous
#include <cuda_runtime.h>
#include <cuda_bf16.h>
#include <stdint.h>

#define NB 64
#define CH 64
#define TT 300
#define VV 25
#define SS 3
#define ICH 16
#define TV 7500
#define KSPLIT 6

// ---------------- scratch ----------------
__device__ __align__(16) __nv_bfloat16 g_T1[SS * NB * ICH * TV];
__device__ __align__(16) __nv_bfloat16 g_T2[SS * NB * ICH * TV];
__device__ __align__(16) uint32_t g_Wb2[9 * 32 * 96];   // conv B: [kt][c2][n96] bf16x2
__device__ __align__(16) uint32_t g_Wh[SS * CH * CH];   // [s][c][o] tf32 (slim-scaled)
__device__ float g_bT1e[SS * ICH];
__device__ float g_bT2e[SS * ICH];
__device__ float g_btot[CH];
__device__ float g_bnscale[CH];
__device__ float g_bnbias[CH];
__device__ float g_Afull[SS * VV * VV];
__device__ float g_partial[KSPLIT * SS * NB * VV * VV];
__device__ float g_A1[SS * NB * VV * VV];

// ---------------- helpers ----------------
__device__ __forceinline__ uint32_t f2tf32(float f) {
    uint32_t r;
    asm("cvt.rna.tf32.f32 %0, %1;" : "=r"(r) : "f"(f));
    return r;
}
__device__ __forceinline__ uint32_t pack_bf16x2(float lo, float hi) {
    uint32_t r;
    asm("cvt.rn.bf16x2.f32 %0, %1, %2;" : "=r"(r) : "f"(hi), "f"(lo));
    return r;
}
__device__ __forceinline__ uint32_t smem_u32(const void* p) {
    uint32_t a;
    asm("{ .reg .u64 t; cvta.to.shared.u64 t, %1; cvt.u32.u64 %0, t; }" : "=r"(a) : "l"(p));
    return a;
}
__device__ __forceinline__ void cp16(uint32_t dst, const void* src) {
    asm volatile("cp.async.cg.shared.global [%0], [%1], 16;" :: "r"(dst), "l"(src));
}
__device__ __forceinline__ void cp_commit() {
    asm volatile("cp.async.commit_group;" ::: "memory");
}
template <int N>
__device__ __forceinline__ void cp_wait() {
    asm volatile("cp.async.wait_group %0;" :: "n"(N) : "memory");
}
__device__ __forceinline__ void mma_bf16(float* c, const uint32_t* a, const uint32_t* b) {
    asm volatile(
        "mma.sync.aligned.m16n8k16.row.col.f32.bf16.bf16.f32 "
        "{%0,%1,%2,%3}, {%4,%5,%6,%7}, {%8,%9}, {%0,%1,%2,%3};"
        : "+f"(c[0]), "+f"(c[1]), "+f"(c[2]), "+f"(c[3])
        : "r"(a[0]), "r"(a[1]), "r"(a[2]), "r"(a[3]), "r"(b[0]), "r"(b[1]));
}
__device__ __forceinline__ void mma_tf32(float* c, const uint32_t* a, const uint32_t* b) {
    asm volatile(
        "mma.sync.aligned.m16n8k8.row.col.f32.tf32.tf32.f32 "
        "{%0,%1,%2,%3}, {%4,%5,%6,%7}, {%8,%9}, {%0,%1,%2,%3};"
        : "+f"(c[0]), "+f"(c[1]), "+f"(c[2]), "+f"(c[3])
        : "r"(a[0]), "r"(a[1]), "r"(a[2]), "r"(a[3]), "r"(b[0]), "r"(b[1]));
}
__device__ __forceinline__ float slim16(int ic, const float* w) {
    if (ic < 9)  return 1.f;
    if (ic < 11) return w[1];
    if (ic < 12) return w[2];
    if (ic < 14) return w[3];
    return w[4];
}
__device__ __forceinline__ float slim64(int o, const float* w) {
    if (o < 38) return 1.f;
    if (o < 44) return w[1];
    if (o < 51) return w[2];
    if (o < 57) return w[3];
    return w[4];
}

// ---------------- prep split (indices 0..2) ----------------
__global__ void prep1_kernel(const float* __restrict__ A, const float* __restrict__ PA)
{
    int tid = threadIdx.x + blockIdx.x * blockDim.x;
    int nt = blockDim.x * gridDim.x;
    for (int i = tid; i < SS * VV * VV; i += nt) {
        float a = A[i];
        float a2 = a * a;
        float ach = 8.f * a2 * a2 - 4.f * a2 - 4.f * a;
        int u = (i / VV) % VV, v = i % VV;
        g_Afull[i] = a + PA[i] + ach + (u == v ? 1.f : 0.f);
    }
}
__global__ void prep2_kernel(const float* __restrict__ w5,
                             const float* __restrict__ WT1, const float* __restrict__ WT2)
{
    int tid = threadIdx.x + blockIdx.x * blockDim.x;
    int nt = blockDim.x * gridDim.x;
    for (int i = tid; i < 9 * 32 * 96; i += nt) {
        int n96 = i % 96;
        int c2 = (i / 96) % 32;
        int kt = i / (96 * 32);
        int s = n96 >> 5;
        int ic2 = n96 & 31;
        int ic = ic2 & 15;
        const float* src = (ic2 < 16) ? WT1 : WT2;
        float sc = slim16(ic, w5);
        float v0 = src[((s * ICH + ic) * CH + 2 * c2) * 9 + kt] * sc;
        float v1 = src[((s * ICH + ic) * CH + 2 * c2 + 1) * 9 + kt] * sc;
        g_Wb2[i] = pack_bf16x2(v0, v1);
    }
}
__global__ void prep3_kernel(const float* __restrict__ w5,
                             const float* __restrict__ Wd, const float* __restrict__ bd,
                             const float* __restrict__ bT1, const float* __restrict__ bT2,
                             const float* __restrict__ bng, const float* __restrict__ bnb,
                             const float* __restrict__ bnm, const float* __restrict__ bnv)
{
    int tid = threadIdx.x + blockIdx.x * blockDim.x;
    int nt = blockDim.x * gridDim.x;
    for (int i = tid; i < SS * ICH; i += nt) {
        int ic = i % ICH;
        float sc = slim16(ic, w5);
        g_bT1e[i] = bT1[i] * sc;
        g_bT2e[i] = bT2[i] * sc;
    }
    for (int i = tid; i < SS * CH * CH; i += nt) {
        int o = i & 63;
        int c = (i >> 6) & 63;
        int s = i >> 12;
        g_Wh[i] = f2tf32(Wd[(s * CH + o) * CH + c] * slim64(o, w5));
    }
    for (int i = tid; i < CH; i += nt) {
        float bt = 0.f;
        for (int s = 0; s < SS; ++s) bt += bd[s * CH + i];
        g_btot[i] = bt * slim64(i, w5);
        float inv = rsqrtf(bnv[i] + 1e-5f);
        float bs = bng[i] * inv;
        g_bnscale[i] = bs;
        g_bnbias[i] = bnb[i] - bnm[i] * bs;
    }
}

// ---------------- bf16 mma conv: t-tile 5, 3-slot ring (index 3) -----------
#define XROWS 328
#define XS2_U32 (32 * XROWS)
#define BSTR 104
#define BS2_U32 (32 * BSTR)
#define CONV_SMEM ((XS2_U32 + 3 * BS2_U32) * 4)

__global__ void __launch_bounds__(256, 2) tc_conv(const float* __restrict__ x)
{
    extern __shared__ uint32_t sm[];
    uint32_t* xs = sm;
    uint32_t* bs = sm + XS2_U32;
    const uint32_t bs_addr = smem_u32(sm) + XS2_U32 * 4;

    const int tid = threadIdx.x;
    const int warp = tid >> 5;
    const int lane = tid & 31;
    const int lr = lane & 3;
    const int lq = lane >> 2;
    const int wm = warp & 3;
    const int wn = warp >> 2;
    const int t0 = blockIdx.x * 5;
    const int n = blockIdx.y;

    for (int c2 = warp; c2 < 32; c2 += 8) {
        const float* x0 = x + ((n * CH + 2 * c2) * TT + (t0 - 4)) * VV;
        for (int r = lane; r < XROWS; r += 32) {
            float v0 = 0.f, v1 = 0.f;
            if (r < 325) {
                int t = t0 - 4 + r / 25;
                if (t >= 0 && t < TT) { v0 = x0[r]; v1 = x0[r + TT * VV]; }
            }
            xs[c2 * XROWS + r] = pack_bf16x2(v0, v1);
        }
    }

#pragma unroll
    for (int j = 0; j < 3; ++j) {
        int f = tid + j * 256;
        int c2 = f / 24, off = (f % 24) * 4;
        cp16(bs_addr + (c2 * BSTR + off) * 4, g_Wb2 + c2 * 96 + off);
    }
    cp_commit();

    float acc[2][6][4];
#pragma unroll
    for (int mi = 0; mi < 2; ++mi)
#pragma unroll
        for (int ni = 0; ni < 6; ++ni)
#pragma unroll
            for (int q = 0; q < 4; ++q) acc[mi][ni][q] = 0.f;

#pragma unroll 1
    for (int kt = 0; kt < 9; ++kt) {
        if (kt < 8) {
            const int wslot = (kt + 1) % 3;
            const uint32_t dstb = bs_addr + wslot * BS2_U32 * 4;
            const uint32_t* src = g_Wb2 + (kt + 1) * 3072;
#pragma unroll
            for (int j = 0; j < 3; ++j) {
                int f = tid + j * 256;
                int c2 = f / 24, off = (f % 24) * 4;
                cp16(dstb + (c2 * BSTR + off) * 4, src + c2 * 96 + off);
            }
            cp_commit();
            cp_wait<1>();
        } else {
            cp_wait<0>();
        }
        __syncthreads();

        const uint32_t* bsl = bs + (kt % 3) * BS2_U32;
        const int rowoff = kt * 25 + lq;

#pragma unroll
        for (int ks = 0; ks < 4; ++ks) {
            const int kb2 = ks * 8;
            uint32_t af[2][4];
#pragma unroll
            for (int mi = 0; mi < 2; ++mi) {
                int R = wm * 32 + mi * 16 + rowoff;
                const uint32_t* p0 = &xs[(kb2 + lr) * XROWS + R];
                af[mi][0] = p0[0];
                af[mi][1] = p0[8];
                af[mi][2] = p0[4 * XROWS];
                af[mi][3] = p0[4 * XROWS + 8];
            }
            uint32_t bf[6][2];
#pragma unroll
            for (int ni = 0; ni < 6; ++ni) {
                int cb = wn * 48 + ni * 8 + lq;
                bf[ni][0] = bsl[(kb2 + lr) * BSTR + cb];
                bf[ni][1] = bsl[(kb2 + lr + 4) * BSTR + cb];
            }
#pragma unroll
            for (int mi = 0; mi < 2; ++mi)
#pragma unroll
                for (int ni = 0; ni < 6; ++ni)
                    mma_bf16(acc[mi][ni], af[mi], bf[ni]);
        }
    }

#pragma unroll
    for (int mi = 0; mi < 2; ++mi) {
        const int rb = wm * 32 + mi * 16 + lq;
#pragma unroll
        for (int ni = 0; ni < 6; ++ni) {
            const int cb = wn * 48 + ni * 8 + 2 * lr;
#pragma unroll
            for (int q = 0; q < 4; ++q) {
                int row = rb + (q >> 1) * 8;
                int col = cb + (q & 1);
                if (row < 125) {
                    int s = col >> 5;
                    int ic2 = col & 31;
                    int ic = ic2 & 15;
                    float bias;
                    __nv_bfloat16* dst;
                    if (ic2 < 16) { bias = g_bT1e[s * ICH + ic]; dst = g_T1; }
                    else          { bias = g_bT2e[s * ICH + ic]; dst = g_T2; }
                    dst[((s * NB + n) * ICH + ic) * TV + t0 * 25 + row] =
                        __float2bfloat16(acc[mi][ni][q] + bias);
                }
            }
        }
    }
}

// ---------------- attention raw scores, bf16 reads (index 4) ----------------
__global__ void __launch_bounds__(128) att_kernel()
{
    __shared__ __align__(16) float t1s[2000];
    __shared__ __align__(16) float t2s[2000];
    const int tid = threadIdx.x;
    const int b = blockIdx.x;
    const int ky = blockIdx.y;
    const uint32_t* p1 = (const uint32_t*)(g_T1 + b * (ICH * TV));
    const uint32_t* p2 = (const uint32_t*)(g_T2 + b * (ICH * TV));

    const bool active = tid < 125;
    const int ks = tid / 25;
    const int tq = (tid % 25) / 5;
    const int tk = tid % 5;

    float acc[5][5];
#pragma unroll
    for (int i = 0; i < 5; ++i)
#pragma unroll
        for (int j = 0; j < 5; ++j) acc[i][j] = 0.f;

#pragma unroll 1
    for (int chk = 0; chk < 10; ++chk) {
        const int off32 = ky * 10000 + chk * 1000;   // u32 index (2 bf16 each)
        __syncthreads();
        for (int i = tid; i < 1000; i += 128) {
            uint32_t w1 = p1[off32 + i];
            uint32_t w2 = p2[off32 + i];
            float2 f1, f2v;
            f1.x = __uint_as_float(w1 << 16);
            f1.y = __uint_as_float(w1 & 0xffff0000u);
            f2v.x = __uint_as_float(w2 << 16);
            f2v.y = __uint_as_float(w2 & 0xffff0000u);
            ((float2*)t1s)[i] = f1;
            ((float2*)t2s)[i] = f2v;
        }
        __syncthreads();
        if (active) {
            const int kb = ks * 16;
#pragma unroll 2
            for (int kl = 0; kl < 16; ++kl) {
                const float* r1 = &t1s[(kb + kl) * 25 + tq * 5];
                const float* r2 = &t2s[(kb + kl) * 25 + tk * 5];
                float t1v[5], t2v[5];
#pragma unroll
                for (int i = 0; i < 5; ++i) t1v[i] = r1[i];
#pragma unroll
                for (int j = 0; j < 5; ++j) t2v[j] = r2[j];
#pragma unroll
                for (int i = 0; i < 5; ++i)
#pragma unroll
                    for (int j = 0; j < 5; ++j)
                        acc[i][j] += t1v[i] * t2v[j];
            }
        }
    }

    float* red = t1s;  // t1s+t2s = 4000 floats >= 3125
    __syncthreads();
    if (active) {
#pragma unroll
        for (int i = 0; i < 5; ++i)
#pragma unroll
            for (int j = 0; j < 5; ++j)
                red[ks * 625 + (tq * 5 + i) * 25 + tk * 5 + j] = acc[i][j];
    }
    __syncthreads();
    const int outb = (ky * (SS * NB) + b) * 625;
    for (int o = tid; o < 625; o += 128) {
        float s = red[o] + red[625 + o] + red[1250 + o] + red[1875 + o] + red[2500 + o];
        g_partial[outb + o] = s;
    }
}

// ---------------- softmax + A1 (index 5) ----------------
__global__ void soft_kernel()
{
    const int b = blockIdx.x;
    const int vk = threadIdx.x;
    if (vk >= 25) return;
    const int s = b / NB;
    float r[25];
    float mx = -1e30f;
    for (int vq = 0; vq < 25; ++vq) {
        float sum = 0.f;
        for (int ky = 0; ky < KSPLIT; ++ky)
            sum += g_partial[(ky * (SS * NB) + b) * 625 + vq * 25 + vk];
        r[vq] = sum * (1.f / 4800.f);
        mx = fmaxf(mx, r[vq]);
    }
    float e = 0.f;
    for (int vq = 0; vq < 25; ++vq) { r[vq] = expf(r[vq] - mx); e += r[vq]; }
    float inv = 1.f / e;
    for (int vq = 0; vq < 25; ++vq)
        g_A1[b * 625 + vq * 25 + vk] = g_Afull[s * 625 + vq * 25 + vk] + r[vq] * inv;
}

// ---------------- fused z: t-tile 5 (index 6) ----------------
#define FZ_XB_STR 136
#define FZ_XB (64 * FZ_XB_STR)
#define FZ_WB_STR 72
#define FZ_WB (64 * FZ_WB_STR)
#define FZ_HS_STR 328
#define FZ_HS (32 * FZ_HS_STR)
#define FZ_A1_STR 36
#define FZ_A1S (32 * FZ_A1_STR)
#define FZ_SMEM ((FZ_XB + FZ_WB + FZ_HS + 3 * FZ_A1S) * 4)

__global__ void __launch_bounds__(256, 2) fz_kernel(const float* __restrict__ x,
                                                    float* __restrict__ out)
{
    extern __shared__ uint32_t smz[];
    uint32_t* xB  = smz;
    uint32_t* wB  = smz + FZ_XB;
    uint32_t* hs  = smz + FZ_XB + FZ_WB;
    uint32_t* a1t = smz + FZ_XB + FZ_WB + FZ_HS;

    const int tid = threadIdx.x;
    const int warp = tid >> 5;
    const int lane = tid & 31;
    const int lr = lane & 3;
    const int lq = lane >> 2;
    const int nt = warp >> 1;
    const int mtb = (warp & 1) * 10;
    const int t0 = blockIdx.x * 5;
    const int p0 = t0 * 25;
    const int n = blockIdx.y;

    for (int i = tid; i < FZ_XB; i += 256) {
        int c = i / FZ_XB_STR, p = i % FZ_XB_STR;
        xB[i] = (p < 125) ? f2tf32(x[(n * CH + c) * TV + p0 + p]) : 0u;
    }
    for (int i = tid; i < 3 * 1024; i += 256) {
        int s = i >> 10;
        int v = (i >> 5) & 31;
        int u = i & 31;
        uint32_t val = 0u;
        if (v < VV && u < VV)
            val = f2tf32(g_A1[(s * NB + n) * 625 + u * 25 + v]);
        a1t[s * FZ_A1S + v * FZ_A1_STR + u] = val;
    }
    for (int i = tid; i < 7 * FZ_HS_STR; i += 256)
        hs[25 * FZ_HS_STR + i] = 0u;

    float acc2[10][4];
#pragma unroll
    for (int ti = 0; ti < 10; ++ti)
#pragma unroll
        for (int q = 0; q < 4; ++q) acc2[ti][q] = 0.f;

#pragma unroll 1
    for (int s = 0; s < SS; ++s) {
        __syncthreads();
        for (int i = tid; i < 4096; i += 256) {
            int c = i >> 6, o = i & 63;
            wB[c * FZ_WB_STR + o] = g_Wh[s * 4096 + i];
        }
        __syncthreads();

        float acc1[8][4];
#pragma unroll
        for (int ni = 0; ni < 8; ++ni)
#pragma unroll
            for (int q = 0; q < 4; ++q) acc1[ni][q] = 0.f;

#pragma unroll
        for (int kk = 0; kk < 8; ++kk) {
            const int kb = kk * 8;
            uint32_t af[4];
            {
                const uint32_t* pA = &xB[(kb + lr) * FZ_XB_STR + warp * 16 + lq];
                af[0] = pA[0];
                af[1] = pA[8];
                af[2] = pA[4 * FZ_XB_STR];
                af[3] = pA[4 * FZ_XB_STR + 8];
            }
#pragma unroll
            for (int ni = 0; ni < 8; ++ni) {
                uint32_t bf[2];
                const uint32_t* pB = &wB[(kb + lr) * FZ_WB_STR + ni * 8 + lq];
                bf[0] = pB[0];
                bf[1] = pB[4 * FZ_WB_STR];
                mma_tf32(acc1[ni], af, bf);
            }
        }

#pragma unroll
        for (int ni = 0; ni < 8; ++ni)
#pragma unroll
            for (int q = 0; q < 4; ++q) {
                int p = warp * 16 + lq + (q >> 1) * 8;
                int o = ni * 8 + 2 * lr + (q & 1);
                if (p < 125) {
                    int tl = p / 25, u = p % 25;
                    hs[u * FZ_HS_STR + tl * 64 + o] = f2tf32(acc1[ni][q]);
                }
            }
        __syncthreads();

#pragma unroll
        for (int kk = 0; kk < 4; ++kk) {
            const int kb = kk * 8;
            uint32_t bf[2];
            {
                const uint32_t* pB = &a1t[s * FZ_A1S + (nt * 8 + lq) * FZ_A1_STR + kb + lr];
                bf[0] = pB[0];
                bf[1] = pB[4];
            }
#pragma unroll
            for (int ti = 0; ti < 10; ++ti) {
                const int mt = mtb + ti;
                uint32_t af[4];
                const uint32_t* pA = &hs[(kb + lr) * FZ_HS_STR + mt * 16 + lq];
                af[0] = pA[0];
                af[1] = pA[8];
                af[2] = pA[4 * FZ_HS_STR];
                af[3] = pA[4 * FZ_HS_STR + 8];
                mma_tf32(acc2[ti], af, bf);
            }
        }
    }

#pragma unroll
    for (int ti = 0; ti < 10; ++ti) {
        const int mt = mtb + ti;
#pragma unroll
        for (int q = 0; q < 4; ++q) {
            int r = mt * 16 + lq + (q >> 1) * 8;
            int v = nt * 8 + 2 * lr + (q & 1);
            if (v < VV) {
                int tl = r >> 6, o = r & 63;
                int gi = ((n * CH + o) * TT + t0 + tl) * VV + v;
                float val = fmaf(acc2[ti][q] + g_btot[o], g_bnscale[o], g_bnbias[o]) + x[gi];
                out[gi] = fmaxf(val, 0.f);
            }
        }
    }
}

// ---------------- launch ----------------
extern "C" void kernel_launch(void* const* d_in, const int* in_sizes, int n_in,
                              void* d_out, int out_size)
{
    const float* x   = (const float*)d_in[0];
    const float* w5  = (const float*)d_in[1];
    const float* A   = (const float*)d_in[2];
    const float* PA  = (const float*)d_in[3];
    const float* Wd  = (const float*)d_in[4];
    const float* bd  = (const float*)d_in[5];
    const float* WT1 = (const float*)d_in[6];
    const float* bT1 = (const float*)d_in[7];
    const float* WT2 = (const float*)d_in[8];
    const float* bT2 = (const float*)d_in[9];
    const float* bng = (const float*)d_in[10];
    const float* bnb = (const float*)d_in[11];
    const float* bnm = (const float*)d_in[12];
    const float* bnv = (const float*)d_in[13];
    float* out = (float*)d_out;

    cudaFuncSetAttribute(tc_conv,  cudaFuncAttributeMaxDynamicSharedMemorySize, CONV_SMEM);
    cudaFuncSetAttribute(fz_kernel, cudaFuncAttributeMaxDynamicSharedMemorySize, FZ_SMEM);

    prep1_kernel<<<2, 256>>>(A, PA);
    prep2_kernel<<<4, 256>>>(w5, WT1, WT2);
    prep3_kernel<<<4, 256>>>(w5, Wd, bd, bT1, bT2, bng, bnb, bnm, bnv);
    tc_conv<<<dim3(60, NB), 256, CONV_SMEM>>>(x);        // profiled slot (index 3)
    att_kernel<<<dim3(SS * NB, KSPLIT), 128>>>();
    soft_kernel<<<SS * NB, 32>>>();
    fz_kernel<<<dim3(60, NB), 256, FZ_SMEM>>>(x, out);
}

// round 16
// speedup vs baseline: 1.1761x; 1.0008x over previous
#include <cuda_runtime.h>
#include <cuda_bf16.h>
#include <stdint.h>

#define NB 64
#define CH 64
#define TT 300
#define VV 25
#define SS 3
#define ICH 16
#define TV 7500
#define KSPLIT 6

// ---------------- scratch ----------------
__device__ __align__(16) __nv_bfloat16 g_T1[SS * NB * ICH * TV];
__device__ __align__(16) __nv_bfloat16 g_T2[SS * NB * ICH * TV];
__device__ __align__(16) uint32_t g_Wb2[9 * 32 * 96];   // conv B: [kt][c2][n96] bf16x2
__device__ __align__(16) uint32_t g_Wh[SS * CH * CH];   // [s][c][o] tf32 (slim-scaled)
__device__ float g_bT1e[SS * ICH];
__device__ float g_bT2e[SS * ICH];
__device__ float g_btot[CH];
__device__ float g_bnscale[CH];
__device__ float g_bnbias[CH];
__device__ float g_Afull[SS * VV * VV];
__device__ float g_partial[KSPLIT * SS * NB * VV * VV];
__device__ float g_A1[SS * NB * VV * VV];

// ---------------- helpers ----------------
__device__ __forceinline__ uint32_t f2tf32(float f) {
    uint32_t r;
    asm("cvt.rna.tf32.f32 %0, %1;" : "=r"(r) : "f"(f));
    return r;
}
__device__ __forceinline__ uint32_t pack_bf16x2(float lo, float hi) {
    uint32_t r;
    asm("cvt.rn.bf16x2.f32 %0, %1, %2;" : "=r"(r) : "f"(hi), "f"(lo));
    return r;
}
__device__ __forceinline__ uint32_t smem_u32(const void* p) {
    uint32_t a;
    asm("{ .reg .u64 t; cvta.to.shared.u64 t, %1; cvt.u32.u64 %0, t; }" : "=r"(a) : "l"(p));
    return a;
}
__device__ __forceinline__ void cp16(uint32_t dst, const void* src) {
    asm volatile("cp.async.cg.shared.global [%0], [%1], 16;" :: "r"(dst), "l"(src));
}
__device__ __forceinline__ void cp_commit() {
    asm volatile("cp.async.commit_group;" ::: "memory");
}
template <int N>
__device__ __forceinline__ void cp_wait() {
    asm volatile("cp.async.wait_group %0;" :: "n"(N) : "memory");
}
__device__ __forceinline__ void mma_bf16(float* c, const uint32_t* a, const uint32_t* b) {
    asm volatile(
        "mma.sync.aligned.m16n8k16.row.col.f32.bf16.bf16.f32 "
        "{%0,%1,%2,%3}, {%4,%5,%6,%7}, {%8,%9}, {%0,%1,%2,%3};"
        : "+f"(c[0]), "+f"(c[1]), "+f"(c[2]), "+f"(c[3])
        : "r"(a[0]), "r"(a[1]), "r"(a[2]), "r"(a[3]), "r"(b[0]), "r"(b[1]));
}
__device__ __forceinline__ void mma_tf32(float* c, const uint32_t* a, const uint32_t* b) {
    asm volatile(
        "mma.sync.aligned.m16n8k8.row.col.f32.tf32.tf32.f32 "
        "{%0,%1,%2,%3}, {%4,%5,%6,%7}, {%8,%9}, {%0,%1,%2,%3};"
        : "+f"(c[0]), "+f"(c[1]), "+f"(c[2]), "+f"(c[3])
        : "r"(a[0]), "r"(a[1]), "r"(a[2]), "r"(a[3]), "r"(b[0]), "r"(b[1]));
}
__device__ __forceinline__ float slim16(int ic, const float* w) {
    if (ic < 9)  return 1.f;
    if (ic < 11) return w[1];
    if (ic < 12) return w[2];
    if (ic < 14) return w[3];
    return w[4];
}
__device__ __forceinline__ float slim64(int o, const float* w) {
    if (o < 38) return 1.f;
    if (o < 44) return w[1];
    if (o < 51) return w[2];
    if (o < 57) return w[3];
    return w[4];
}

// ---------------- prep split (indices 0..2) ----------------
__global__ void prep1_kernel(const float* __restrict__ A, const float* __restrict__ PA)
{
    int tid = threadIdx.x + blockIdx.x * blockDim.x;
    int nt = blockDim.x * gridDim.x;
    for (int i = tid; i < SS * VV * VV; i += nt) {
        float a = A[i];
        float a2 = a * a;
        float ach = 8.f * a2 * a2 - 4.f * a2 - 4.f * a;
        int u = (i / VV) % VV, v = i % VV;
        g_Afull[i] = a + PA[i] + ach + (u == v ? 1.f : 0.f);
    }
}
__global__ void prep2_kernel(const float* __restrict__ w5,
                             const float* __restrict__ WT1, const float* __restrict__ WT2)
{
    int tid = threadIdx.x + blockIdx.x * blockDim.x;
    int nt = blockDim.x * gridDim.x;
    for (int i = tid; i < 9 * 32 * 96; i += nt) {
        int n96 = i % 96;
        int c2 = (i / 96) % 32;
        int kt = i / (96 * 32);
        int s = n96 >> 5;
        int ic2 = n96 & 31;
        int ic = ic2 & 15;
        const float* src = (ic2 < 16) ? WT1 : WT2;
        float sc = slim16(ic, w5);
        float v0 = src[((s * ICH + ic) * CH + 2 * c2) * 9 + kt] * sc;
        float v1 = src[((s * ICH + ic) * CH + 2 * c2 + 1) * 9 + kt] * sc;
        g_Wb2[i] = pack_bf16x2(v0, v1);
    }
}
__global__ void prep3_kernel(const float* __restrict__ w5,
                             const float* __restrict__ Wd, const float* __restrict__ bd,
                             const float* __restrict__ bT1, const float* __restrict__ bT2,
                             const float* __restrict__ bng, const float* __restrict__ bnb,
                             const float* __restrict__ bnm, const float* __restrict__ bnv)
{
    int tid = threadIdx.x + blockIdx.x * blockDim.x;
    int nt = blockDim.x * gridDim.x;
    for (int i = tid; i < SS * ICH; i += nt) {
        int ic = i % ICH;
        float sc = slim16(ic, w5);
        g_bT1e[i] = bT1[i] * sc;
        g_bT2e[i] = bT2[i] * sc;
    }
    for (int i = tid; i < SS * CH * CH; i += nt) {
        int o = i & 63;
        int c = (i >> 6) & 63;
        int s = i >> 12;
        g_Wh[i] = f2tf32(Wd[(s * CH + o) * CH + c] * slim64(o, w5));
    }
    for (int i = tid; i < CH; i += nt) {
        float bt = 0.f;
        for (int s = 0; s < SS; ++s) bt += bd[s * CH + i];
        g_btot[i] = bt * slim64(i, w5);
        float inv = rsqrtf(bnv[i] + 1e-5f);
        float bs = bng[i] * inv;
        g_bnscale[i] = bs;
        g_bnbias[i] = bnb[i] - bnm[i] * bs;
    }
}

// ---------------- bf16 mma conv: t-tile 5, 3-slot ring (index 3) -----------
#define XROWS 328
#define XS2_U32 (32 * XROWS)
#define BSTR 104
#define BS2_U32 (32 * BSTR)
#define CONV_SMEM ((XS2_U32 + 3 * BS2_U32) * 4)

__global__ void __launch_bounds__(256, 2) tc_conv(const float* __restrict__ x)
{
    extern __shared__ uint32_t sm[];
    uint32_t* xs = sm;
    uint32_t* bs = sm + XS2_U32;
    const uint32_t bs_addr = smem_u32(sm) + XS2_U32 * 4;

    const int tid = threadIdx.x;
    const int warp = tid >> 5;
    const int lane = tid & 31;
    const int lr = lane & 3;
    const int lq = lane >> 2;
    const int wm = warp & 3;
    const int wn = warp >> 2;
    const int t0 = blockIdx.x * 5;
    const int n = blockIdx.y;

    for (int c2 = warp; c2 < 32; c2 += 8) {
        const float* x0 = x + ((n * CH + 2 * c2) * TT + (t0 - 4)) * VV;
        for (int r = lane; r < XROWS; r += 32) {
            float v0 = 0.f, v1 = 0.f;
            if (r < 325) {
                int t = t0 - 4 + r / 25;
                if (t >= 0 && t < TT) { v0 = x0[r]; v1 = x0[r + TT * VV]; }
            }
            xs[c2 * XROWS + r] = pack_bf16x2(v0, v1);
        }
    }

#pragma unroll
    for (int j = 0; j < 3; ++j) {
        int f = tid + j * 256;
        int c2 = f / 24, off = (f % 24) * 4;
        cp16(bs_addr + (c2 * BSTR + off) * 4, g_Wb2 + c2 * 96 + off);
    }
    cp_commit();

    float acc[2][6][4];
#pragma unroll
    for (int mi = 0; mi < 2; ++mi)
#pragma unroll
        for (int ni = 0; ni < 6; ++ni)
#pragma unroll
            for (int q = 0; q < 4; ++q) acc[mi][ni][q] = 0.f;

#pragma unroll 1
    for (int kt = 0; kt < 9; ++kt) {
        if (kt < 8) {
            const int wslot = (kt + 1) % 3;
            const uint32_t dstb = bs_addr + wslot * BS2_U32 * 4;
            const uint32_t* src = g_Wb2 + (kt + 1) * 3072;
#pragma unroll
            for (int j = 0; j < 3; ++j) {
                int f = tid + j * 256;
                int c2 = f / 24, off = (f % 24) * 4;
                cp16(dstb + (c2 * BSTR + off) * 4, src + c2 * 96 + off);
            }
            cp_commit();
            cp_wait<1>();
        } else {
            cp_wait<0>();
        }
        __syncthreads();

        const uint32_t* bsl = bs + (kt % 3) * BS2_U32;
        const int rowoff = kt * 25 + lq;

#pragma unroll
        for (int ks = 0; ks < 4; ++ks) {
            const int kb2 = ks * 8;
            uint32_t af[2][4];
#pragma unroll
            for (int mi = 0; mi < 2; ++mi) {
                int R = wm * 32 + mi * 16 + rowoff;
                const uint32_t* p0 = &xs[(kb2 + lr) * XROWS + R];
                af[mi][0] = p0[0];
                af[mi][1] = p0[8];
                af[mi][2] = p0[4 * XROWS];
                af[mi][3] = p0[4 * XROWS + 8];
            }
            uint32_t bf[6][2];
#pragma unroll
            for (int ni = 0; ni < 6; ++ni) {
                int cb = wn * 48 + ni * 8 + lq;
                bf[ni][0] = bsl[(kb2 + lr) * BSTR + cb];
                bf[ni][1] = bsl[(kb2 + lr + 4) * BSTR + cb];
            }
#pragma unroll
            for (int mi = 0; mi < 2; ++mi)
#pragma unroll
                for (int ni = 0; ni < 6; ++ni)
                    mma_bf16(acc[mi][ni], af[mi], bf[ni]);
        }
    }

#pragma unroll
    for (int mi = 0; mi < 2; ++mi) {
        const int rb = wm * 32 + mi * 16 + lq;
#pragma unroll
        for (int ni = 0; ni < 6; ++ni) {
            const int cb = wn * 48 + ni * 8 + 2 * lr;
#pragma unroll
            for (int q = 0; q < 4; ++q) {
                int row = rb + (q >> 1) * 8;
                int col = cb + (q & 1);
                if (row < 125) {
                    int s = col >> 5;
                    int ic2 = col & 31;
                    int ic = ic2 & 15;
                    float bias;
                    __nv_bfloat16* dst;
                    if (ic2 < 16) { bias = g_bT1e[s * ICH + ic]; dst = g_T1; }
                    else          { bias = g_bT2e[s * ICH + ic]; dst = g_T2; }
                    dst[((s * NB + n) * ICH + ic) * TV + t0 * 25 + row] =
                        __float2bfloat16(acc[mi][ni][q] + bias);
                }
            }
        }
    }
}

// ---------------- attention raw scores, bf16 reads (index 4) ----------------
__global__ void __launch_bounds__(128) att_kernel()
{
    __shared__ __align__(16) float t1s[2000];
    __shared__ __align__(16) float t2s[2000];
    const int tid = threadIdx.x;
    const int b = blockIdx.x;
    const int ky = blockIdx.y;
    const uint32_t* p1 = (const uint32_t*)(g_T1 + b * (ICH * TV));
    const uint32_t* p2 = (const uint32_t*)(g_T2 + b * (ICH * TV));

    const bool active = tid < 125;
    const int ks = tid / 25;
    const int tq = (tid % 25) / 5;
    const int tk = tid % 5;

    float acc[5][5];
#pragma unroll
    for (int i = 0; i < 5; ++i)
#pragma unroll
        for (int j = 0; j < 5; ++j) acc[i][j] = 0.f;

#pragma unroll 1
    for (int chk = 0; chk < 10; ++chk) {
        const int off32 = ky * 10000 + chk * 1000;   // u32 index (2 bf16 each)
        __syncthreads();
        for (int i = tid; i < 1000; i += 128) {
            uint32_t w1 = p1[off32 + i];
            uint32_t w2 = p2[off32 + i];
            float2 f1, f2v;
            f1.x = __uint_as_float(w1 << 16);
            f1.y = __uint_as_float(w1 & 0xffff0000u);
            f2v.x = __uint_as_float(w2 << 16);
            f2v.y = __uint_as_float(w2 & 0xffff0000u);
            ((float2*)t1s)[i] = f1;
            ((float2*)t2s)[i] = f2v;
        }
        __syncthreads();
        if (active) {
            const int kb = ks * 16;
#pragma unroll 2
            for (int kl = 0; kl < 16; ++kl) {
                const float* r1 = &t1s[(kb + kl) * 25 + tq * 5];
                const float* r2 = &t2s[(kb + kl) * 25 + tk * 5];
                float t1v[5], t2v[5];
#pragma unroll
                for (int i = 0; i < 5; ++i) t1v[i] = r1[i];
#pragma unroll
                for (int j = 0; j < 5; ++j) t2v[j] = r2[j];
#pragma unroll
                for (int i = 0; i < 5; ++i)
#pragma unroll
                    for (int j = 0; j < 5; ++j)
                        acc[i][j] += t1v[i] * t2v[j];
            }
        }
    }

    float* red = t1s;  // t1s+t2s = 4000 floats >= 3125
    __syncthreads();
    if (active) {
#pragma unroll
        for (int i = 0; i < 5; ++i)
#pragma unroll
            for (int j = 0; j < 5; ++j)
                red[ks * 625 + (tq * 5 + i) * 25 + tk * 5 + j] = acc[i][j];
    }
    __syncthreads();
    const int outb = (ky * (SS * NB) + b) * 625;
    for (int o = tid; o < 625; o += 128) {
        float s = red[o] + red[625 + o] + red[1250 + o] + red[1875 + o] + red[2500 + o];
        g_partial[outb + o] = s;
    }
}

// ---------------- softmax + A1 (index 5) ----------------
__global__ void soft_kernel()
{
    const int b = blockIdx.x;
    const int vk = threadIdx.x;
    if (vk >= 25) return;
    const int s = b / NB;
    float r[25];
    float mx = -1e30f;
    for (int vq = 0; vq < 25; ++vq) {
        float sum = 0.f;
        for (int ky = 0; ky < KSPLIT; ++ky)
            sum += g_partial[(ky * (SS * NB) + b) * 625 + vq * 25 + vk];
        r[vq] = sum * (1.f / 4800.f);
        mx = fmaxf(mx, r[vq]);
    }
    float e = 0.f;
    for (int vq = 0; vq < 25; ++vq) { r[vq] = expf(r[vq] - mx); e += r[vq]; }
    float inv = 1.f / e;
    for (int vq = 0; vq < 25; ++vq)
        g_A1[b * 625 + vq * 25 + vk] = g_Afull[s * 625 + vq * 25 + vk] + r[vq] * inv;
}

// ---------------- fused z: t-tile 5 (index 6) ----------------
#define FZ_XB_STR 136
#define FZ_XB (64 * FZ_XB_STR)
#define FZ_WB_STR 72
#define FZ_WB (64 * FZ_WB_STR)
#define FZ_HS_STR 328
#define FZ_HS (32 * FZ_HS_STR)
#define FZ_A1_STR 36
#define FZ_A1S (32 * FZ_A1_STR)
#define FZ_SMEM ((FZ_XB + FZ_WB + FZ_HS + 3 * FZ_A1S) * 4)

__global__ void __launch_bounds__(256, 2) fz_kernel(const float* __restrict__ x,
                                                    float* __restrict__ out)
{
    extern __shared__ uint32_t smz[];
    uint32_t* xB  = smz;
    uint32_t* wB  = smz + FZ_XB;
    uint32_t* hs  = smz + FZ_XB + FZ_WB;
    uint32_t* a1t = smz + FZ_XB + FZ_WB + FZ_HS;

    const int tid = threadIdx.x;
    const int warp = tid >> 5;
    const int lane = tid & 31;
    const int lr = lane & 3;
    const int lq = lane >> 2;
    const int nt = warp >> 1;
    const int mtb = (warp & 1) * 10;
    const int t0 = blockIdx.x * 5;
    const int p0 = t0 * 25;
    const int n = blockIdx.y;

    for (int i = tid; i < FZ_XB; i += 256) {
        int c = i / FZ_XB_STR, p = i % FZ_XB_STR;
        xB[i] = (p < 125) ? f2tf32(x[(n * CH + c) * TV + p0 + p]) : 0u;
    }
    for (int i = tid; i < 3 * 1024; i += 256) {
        int s = i >> 10;
        int v = (i >> 5) & 31;
        int u = i & 31;
        uint32_t val = 0u;
        if (v < VV && u < VV)
            val = f2tf32(g_A1[(s * NB + n) * 625 + u * 25 + v]);
        a1t[s * FZ_A1S + v * FZ_A1_STR + u] = val;
    }
    for (int i = tid; i < 7 * FZ_HS_STR; i += 256)
        hs[25 * FZ_HS_STR + i] = 0u;

    float acc2[10][4];
#pragma unroll
    for (int ti = 0; ti < 10; ++ti)
#pragma unroll
        for (int q = 0; q < 4; ++q) acc2[ti][q] = 0.f;

#pragma unroll 1
    for (int s = 0; s < SS; ++s) {
        __syncthreads();
        for (int i = tid; i < 4096; i += 256) {
            int c = i >> 6, o = i & 63;
            wB[c * FZ_WB_STR + o] = g_Wh[s * 4096 + i];
        }
        __syncthreads();

        float acc1[8][4];
#pragma unroll
        for (int ni = 0; ni < 8; ++ni)
#pragma unroll
            for (int q = 0; q < 4; ++q) acc1[ni][q] = 0.f;

#pragma unroll
        for (int kk = 0; kk < 8; ++kk) {
            const int kb = kk * 8;
            uint32_t af[4];
            {
                const uint32_t* pA = &xB[(kb + lr) * FZ_XB_STR + warp * 16 + lq];
                af[0] = pA[0];
                af[1] = pA[8];
                af[2] = pA[4 * FZ_XB_STR];
                af[3] = pA[4 * FZ_XB_STR + 8];
            }
#pragma unroll
            for (int ni = 0; ni < 8; ++ni) {
                uint32_t bf[2];
                const uint32_t* pB = &wB[(kb + lr) * FZ_WB_STR + ni * 8 + lq];
                bf[0] = pB[0];
                bf[1] = pB[4 * FZ_WB_STR];
                mma_tf32(acc1[ni], af, bf);
            }
        }

#pragma unroll
        for (int ni = 0; ni < 8; ++ni)
#pragma unroll
            for (int q = 0; q < 4; ++q) {
                int p = warp * 16 + lq + (q >> 1) * 8;
                int o = ni * 8 + 2 * lr + (q & 1);
                if (p < 125) {
                    int tl = p / 25, u = p % 25;
                    hs[u * FZ_HS_STR + tl * 64 + o] = f2tf32(acc1[ni][q]);
                }
            }
        __syncthreads();

#pragma unroll
        for (int kk = 0; kk < 4; ++kk) {
            const int kb = kk * 8;
            uint32_t bf[2];
            {
                const uint32_t* pB = &a1t[s * FZ_A1S + (nt * 8 + lq) * FZ_A1_STR + kb + lr];
                bf[0] = pB[0];
                bf[1] = pB[4];
            }
#pragma unroll
            for (int ti = 0; ti < 10; ++ti) {
                const int mt = mtb + ti;
                uint32_t af[4];
                const uint32_t* pA = &hs[(kb + lr) * FZ_HS_STR + mt * 16 + lq];
                af[0] = pA[0];
                af[1] = pA[8];
                af[2] = pA[4 * FZ_HS_STR];
                af[3] = pA[4 * FZ_HS_STR + 8];
                mma_tf32(acc2[ti], af, bf);
            }
        }
    }

#pragma unroll
    for (int ti = 0; ti < 10; ++ti) {
        const int mt = mtb + ti;
#pragma unroll
        for (int q = 0; q < 4; ++q) {
            int r = mt * 16 + lq + (q >> 1) * 8;
            int v = nt * 8 + 2 * lr + (q & 1);
            if (v < VV) {
                int tl = r >> 6, o = r & 63;
                int gi = ((n * CH + o) * TT + t0 + tl) * VV + v;
                float val = fmaf(acc2[ti][q] + g_btot[o], g_bnscale[o], g_bnbias[o]) + x[gi];
                out[gi] = fmaxf(val, 0.f);
            }
        }
    }
}

// ---------------- launch ----------------
extern "C" void kernel_launch(void* const* d_in, const int* in_sizes, int n_in,
                              void* d_out, int out_size)
{
    const float* x   = (const float*)d_in[0];
    const float* w5  = (const float*)d_in[1];
    const float* A   = (const float*)d_in[2];
    const float* PA  = (const float*)d_in[3];
    const float* Wd  = (const float*)d_in[4];
    const float* bd  = (const float*)d_in[5];
    const float* WT1 = (const float*)d_in[6];
    const float* bT1 = (const float*)d_in[7];
    const float* WT2 = (const float*)d_in[8];
    const float* bT2 = (const float*)d_in[9];
    const float* bng = (const float*)d_in[10];
    const float* bnb = (const float*)d_in[11];
    const float* bnm = (const float*)d_in[12];
    const float* bnv = (const float*)d_in[13];
    float* out = (float*)d_out;

    cudaFuncSetAttribute(tc_conv,  cudaFuncAttributeMaxDynamicSharedMemorySize, CONV_SMEM);
    cudaFuncSetAttribute(fz_kernel, cudaFuncAttributeMaxDynamicSharedMemorySize, FZ_SMEM);

    prep1_kernel<<<2, 256>>>(A, PA);
    prep2_kernel<<<4, 256>>>(w5, WT1, WT2);
    prep3_kernel<<<4, 256>>>(w5, Wd, bd, bT1, bT2, bng, bnb, bnm, bnv);
    tc_conv<<<dim3(60, NB), 256, CONV_SMEM>>>(x);        // profiled slot (index 3)
    att_kernel<<<dim3(SS * NB, KSPLIT), 128>>>();
    soft_kernel<<<SS * NB, 32>>>();
    fz_kernel<<<dim3(60, NB), 256, FZ_SMEM>>>(x, out);
}